// round 10
// baseline (speedup 1.0000x reference)
#include <cuda_runtime.h>
#include <cuda_fp16.h>
#include <cstdint>

#define T_STEPS 512
#define BATCH   128
#define HID     512
#define GCOLS   2048   // 4*HID, interleaved: j = 4*h + gate (0=f,1=i,2=g,3=o)
#define KDIM    512

// ---------------- static device scratch ----------------
// fp16 fragment-packed layouts (m16n8k16). Chunk = 32 lanes x 4 uint32 = 512B.
__device__ __align__(256) uint32_t g_Xh[4096u * 32 * 128];     // X fp16 frags (64MB) [mgrp][ksl][lane][4]
__device__ __align__(256) uint32_t g_Wxh[128 * 32 * 128];      // Wx fp16 frags [n16][ksl][lane][4]
__device__ __align__(256) uint32_t g_Whh[128 * 32 * 128];      // Wh fp16 frags [n16][ksl][lane][4]
__device__ __align__(256) float    g_bias[GCOLS];
__device__ __align__(256) float    g_pre[(size_t)T_STEPS * BATCH * GCOLS];  // x-proj + bias (fp32)
__device__ __align__(256) uint32_t g_hFh[2][8 * 32 * 128];     // h fp16 frags [mg][ksl][lane][4], dbl-buf
__device__ unsigned int g_bar[4];                              // per-batch-group step barrier
__device__ unsigned int g_tcnt[T_STEPS];                       // pre[t] readiness: 32 tiles each

// ---------------- helpers ----------------
__device__ __forceinline__ void cp16(void* s, const void* g) {
    uint32_t sa = (uint32_t)__cvta_generic_to_shared(s);
    asm volatile("cp.async.cg.shared.global [%0], [%1], 16;" :: "r"(sa), "l"(g));
}
__device__ __forceinline__ void cp_commit() { asm volatile("cp.async.commit_group;"); }
__device__ __forceinline__ void cp_wait0()  { asm volatile("cp.async.wait_group 0;"); }
__device__ __forceinline__ void cp_wait1()  { asm volatile("cp.async.wait_group 1;"); }

__device__ __forceinline__ void mma16(float* d, const uint32_t* a, uint32_t b0, uint32_t b1) {
    asm volatile(
        "mma.sync.aligned.m16n8k16.row.col.f32.f16.f16.f32 "
        "{%0,%1,%2,%3}, {%4,%5,%6,%7}, {%8,%9}, {%0,%1,%2,%3};"
        : "+f"(d[0]), "+f"(d[1]), "+f"(d[2]), "+f"(d[3])
        : "r"(a[0]), "r"(a[1]), "r"(a[2]), "r"(a[3]), "r"(b0), "r"(b1));
}

__device__ __forceinline__ float sigf(float x) {
    return __fdividef(1.0f, 1.0f + __expf(-x));
}
__device__ __forceinline__ float tanhfast(float x) {
    float e = __expf(2.0f * x);
    return 1.0f - __fdividef(2.0f, e + 1.0f);
}
__device__ __forceinline__ uint32_t packh2(float lo, float hi) {
    return ((uint32_t)__half_as_ushort(__float2half_rn(hi)) << 16)
         | (uint32_t)__half_as_ushort(__float2half_rn(lo));
}

__device__ __forceinline__ void red_release(unsigned int* p) {
    asm volatile("red.release.gpu.add.u32 [%0], %1;" :: "l"(p), "r"(1u) : "memory");
}
__device__ __forceinline__ unsigned int ld_acq(unsigned int* p) {
    unsigned int v;
    asm volatile("ld.acquire.gpu.u32 %0, [%1];" : "=r"(v) : "l"(p) : "memory");
    return v;
}

// ---------------- pack: Wx + Wh fp16 frags + bias ----------------
__global__ void pack_w(const float* __restrict__ Wf, const float* __restrict__ bf,
                       const float* __restrict__ Wi, const float* __restrict__ bi,
                       const float* __restrict__ Wg, const float* __restrict__ bg_,
                       const float* __restrict__ Wo, const float* __restrict__ bo) {
    unsigned idx = blockIdx.x * 256u + threadIdx.x;  // 0..524287
    int reg = idx & 3, lane = (idx >> 2) & 31, ksl = (idx >> 7) & 31, n16 = idx >> 12;
    int g = lane >> 2, t = lane & 3;
    int n = n16 * 16 + (reg >> 1) * 8 + g;         // B-frag: reg>>1 selects n8 half
    int kb = ksl * 16 + (reg & 1) * 8 + 2 * t;     // reg&1 selects k half (b0/b1)
    int h = n >> 2, gate = n & 3;
    const float* W = (gate == 0) ? Wf : (gate == 1) ? Wi : (gate == 2) ? Wg : Wo;
    g_Wxh[idx] = packh2(W[h * 1024 + kb],       W[h * 1024 + kb + 1]);
    g_Whh[idx] = packh2(W[h * 1024 + 512 + kb], W[h * 1024 + 512 + kb + 1]);
    if (idx < GCOLS) {
        int j = idx, h2 = j >> 2, g2 = j & 3;
        const float* bb = (g2 == 0) ? bf : (g2 == 1) ? bi : (g2 == 2) ? bg_ : bo;
        g_bias[j] = bb[h2];
    }
}

// ---------------- pack: X fp16 frags ----------------
__global__ void pack_x(const float* __restrict__ X) {
    unsigned idx = blockIdx.x * 256u + threadIdx.x;  // 0..16777215
    int reg = idx & 3, lane = (idx >> 2) & 31, ksl = (idx >> 7) & 31;
    unsigned mgrp = idx >> 12;
    int g = lane >> 2, t = lane & 3;
    unsigned m = mgrp * 16 + (reg & 1) * 8 + g;    // A-frag: reg&1 selects row half
    int kb = ksl * 16 + (reg >> 1) * 8 + 2 * t;    // reg>>1 selects k half
    const float* p = X + (size_t)m * 512 + kb;
    g_Xh[idx] = packh2(p[0], p[1]);
}

__global__ void init_state() {
    unsigned i = blockIdx.x * 256u + threadIdx.x;
    if (i < 4) g_bar[i] = 0;
    if (i < T_STEPS) g_tcnt[i] = 0;
    if (i < 2u * 8 * 32 * 128) ((uint32_t*)g_hFh)[i] = 0u;
}

// ---------------- precompute GEMM: pre = X @ WxT + bias (R5-exact + readiness flag) ----------------
// BM=64 BN=128 BK=32, 256 threads, warps 2(M) x 4(N), warp tile 32x32. n-fastest grid.
// Runs CONCURRENTLY with lstm_persist; publishes per-timestep readiness in g_tcnt.
__global__ __launch_bounds__(256) void gemm_pre() {
    __shared__ __align__(128) uint32_t Asm[2][8 * 128];    // 4 mgrp x 2 ksl chunks
    __shared__ __align__(128) uint32_t Bsm[2][16 * 128];   // 8 n16  x 2 ksl chunks
    const int tid = threadIdx.x;
    const int n16_0 = blockIdx.x * 8;        // n0 = blockIdx.x*128
    const int mgrp0 = blockIdx.y * 4;        // m0 = blockIdx.y*64
    const int n0 = n16_0 * 16, m0 = mgrp0 * 16;
    const int warp = tid >> 5, lane = tid & 31;
    const int wm = warp >> 2, wn = warp & 3;
    const int gid = lane >> 2, tig = lane & 3;

    float acc[2][4][4];
    #pragma unroll
    for (int i0 = 0; i0 < 2; i0++)
        #pragma unroll
        for (int i1 = 0; i1 < 4; i1++)
            #pragma unroll
            for (int i2 = 0; i2 < 4; i2++) acc[i0][i1][i2] = 0.0f;

    auto load_tiles = [&](int buf, int kt) {
        {   // A: 8 chunks, 1 slot per thread
            int chunk = tid >> 5, ln = tid & 31;
            unsigned gc = (mgrp0 + (chunk >> 1)) * 32u + 2 * kt + (chunk & 1);
            cp16(&Asm[buf][chunk * 128 + ln * 4], g_Xh + (size_t)gc * 128 + ln * 4);
        }
        #pragma unroll
        for (int i = 0; i < 2; i++) {   // B: 16 chunks, 2 slots per thread
            int slot = tid * 2 + i;
            int chunk = slot >> 5, ln = slot & 31;
            unsigned gc = (n16_0 + (chunk >> 1)) * 32u + 2 * kt + (chunk & 1);
            cp16(&Bsm[buf][chunk * 128 + ln * 4], g_Wxh + (size_t)gc * 128 + ln * 4);
        }
        cp_commit();
    };

    load_tiles(0, 0);
    for (int kt = 0; kt < 16; kt++) {
        if (kt < 15) { load_tiles((kt + 1) & 1, kt + 1); cp_wait1(); }
        else cp_wait0();
        __syncthreads();
        const uint32_t* A_ = Asm[kt & 1];
        const uint32_t* B_ = Bsm[kt & 1];
        #pragma unroll
        for (int ksll = 0; ksll < 2; ksll++) {
            uint4 av0 = *(const uint4*)&A_[((wm * 2 + 0) * 2 + ksll) * 128 + lane * 4];
            uint4 av1 = *(const uint4*)&A_[((wm * 2 + 1) * 2 + ksll) * 128 + lane * 4];
            uint32_t A0[4] = {av0.x, av0.y, av0.z, av0.w};
            uint32_t A1[4] = {av1.x, av1.y, av1.z, av1.w};
            #pragma unroll
            for (int cl = 0; cl < 2; cl++) {
                uint4 bv = *(const uint4*)&B_[((wn * 2 + cl) * 2 + ksll) * 128 + lane * 4];
                mma16(acc[0][cl * 2 + 0], A0, bv.x, bv.y);
                mma16(acc[0][cl * 2 + 1], A0, bv.z, bv.w);
                mma16(acc[1][cl * 2 + 0], A1, bv.x, bv.y);
                mma16(acc[1][cl * 2 + 1], A1, bv.z, bv.w);
            }
        }
        __syncthreads();
    }

    #pragma unroll
    for (int mf = 0; mf < 2; mf++)
        #pragma unroll
        for (int nf = 0; nf < 4; nf++) {
            int row0 = m0 + wm * 32 + mf * 16 + gid;
            int col  = n0 + wn * 32 + nf * 8 + tig * 2;
            float bb0 = g_bias[col], bb1 = g_bias[col + 1];
            float2 s0 = make_float2(acc[mf][nf][0] + bb0, acc[mf][nf][1] + bb1);
            float2 s1 = make_float2(acc[mf][nf][2] + bb0, acc[mf][nf][3] + bb1);
            *(float2*)&g_pre[(size_t)row0 * GCOLS + col]       = s0;
            *(float2*)&g_pre[(size_t)(row0 + 8) * GCOLS + col] = s1;
        }

    // publish: this tile (one of 32) of timestep blockIdx.y>>1 is complete
    __syncthreads();
    if (tid == 0) red_release(&g_tcnt[blockIdx.y >> 1]);
}

// ---------------- persistent recurrent kernel (R5-exact + pre-readiness waits) ----------------
// Grid: 128 blocks = 4 batch-groups x 32 n-slices. 256 threads (8 warps = S4 x Q2).
__global__ __launch_bounds__(256) void lstm_persist(float* __restrict__ out) {
    extern __shared__ uint32_t sm32[];
    uint32_t* WhS = sm32;                    // 16384 u32 (64KB): [n16l(4)][ksl(32)][lane][4]
    uint32_t* As  = sm32 + 16384;            // 8192 u32 (32KB): [mgl(2)][ksl(32)][lane][4]
    float* redbuf  = (float*)As;             // reuse (6144 floats <= 8192 u32)
    float* gatebuf = (float*)(sm32 + 16384 + 8192);   // 2176 floats

    const int tid  = threadIdx.x;
    const int lane = tid & 31;
    const int w    = tid >> 5;
    const int ws   = w >> 1;         // k-slice 0..3 (k range 128)
    const int wq   = w & 1;          // n-half 0..1
    const int gid  = lane >> 2, tig = lane & 3;

    const int bg  = blockIdx.x >> 5;       // batch group 0..3
    const int nb  = blockIdx.x & 31;       // n-slice 0..31
    const int b0_ = bg * 32;
    const int n0  = nb * 64;

    // --- load Wh slice (64KB = 4096 cp16 / 256 thr = 16 each) ---
    {
        const uint32_t* src = g_Whh + (size_t)nb * 16384;
        #pragma unroll
        for (int i = 0; i < 16; i++) {
            int c = tid + i * 256;
            cp16(&WhS[c * 4], src + (size_t)c * 4);
        }
        cp_commit(); cp_wait0();
        __syncthreads();
    }

    // epilogue cell mapping (fixed): 2 cells (bglob, hg), (bglob, hg+1)
    const int b_loc = tid >> 3;            // 0..31
    const int hloc0 = (tid & 7) * 2;       // 0..14 even
    const int bglob = b0_ + b_loc;
    const int hg    = nb * 16 + hloc0;
    // h frag-layout offset: both cells share one uint32 (k pair)
    const int mg_h = bglob >> 4;
    const int rr   = bglob & 15;
    const int g_m  = rr & 7, hi_m = rr >> 3;
    const int ksl_h = hg >> 4;
    const int kk   = hg & 15;
    const int hi_k = kk >> 3, tig_k = (kk >> 1) & 3;
    const int hoff32 = ((mg_h * 32 + ksl_h) * 32 + (g_m * 4 + tig_k)) * 4 + (hi_m + 2 * hi_k);

    float c0 = 0.0f, c1 = 0.0f;

    // wait for pre[0] readiness, then prefetch
    if (tid == 0) { while (ld_acq(&g_tcnt[0]) < 32u) { } }
    __syncthreads();
    const float* prbase = g_pre + (size_t)bglob * GCOLS + n0 + hloc0 * 4;
    float4 pA = *(const float4*)prbase;
    float4 pB = *(const float4*)(prbase + 4);

    for (int t = 0; t < T_STEPS; t++) {
        const int rb = t & 1, wb = rb ^ 1;

        // --- stage h[rb]: 32KB = 2048 cp16 / 256 thr = 8 each ---
        const uint32_t* src = g_hFh[rb] + bg * 8192;
        #pragma unroll
        for (int i = 0; i < 8; i++) {
            int c = tid + i * 256;
            cp16(&As[c * 4], src + c * 4);
        }
        cp_commit();
        cp_wait0();
        __syncthreads();

        // --- mainloop: warp (ws,wq): 32m x 32n, k in [ws*128, +128) ---
        float acc[2][4][4];
        #pragma unroll
        for (int i0 = 0; i0 < 2; i0++)
            #pragma unroll
            for (int i1 = 0; i1 < 4; i1++)
                #pragma unroll
                for (int i2 = 0; i2 < 4; i2++) acc[i0][i1][i2] = 0.0f;

        #pragma unroll
        for (int ksl = 0; ksl < 8; ksl++) {
            const int kg = ws * 8 + ksl;
            uint4 a0v = *(const uint4*)&As[(0 * 32 + kg) * 128 + lane * 4];
            uint4 a1v = *(const uint4*)&As[(1 * 32 + kg) * 128 + lane * 4];
            uint4 b0v = *(const uint4*)&WhS[((wq * 2 + 0) * 32 + kg) * 128 + lane * 4];
            uint4 b1v = *(const uint4*)&WhS[((wq * 2 + 1) * 32 + kg) * 128 + lane * 4];
            uint32_t A0[4] = {a0v.x, a0v.y, a0v.z, a0v.w};
            uint32_t A1[4] = {a1v.x, a1v.y, a1v.z, a1v.w};
            mma16(acc[0][0], A0, b0v.x, b0v.y);
            mma16(acc[0][1], A0, b0v.z, b0v.w);
            mma16(acc[0][2], A0, b1v.x, b1v.y);
            mma16(acc[0][3], A0, b1v.z, b1v.w);
            mma16(acc[1][0], A1, b0v.x, b0v.y);
            mma16(acc[1][1], A1, b0v.z, b0v.w);
            mma16(acc[1][2], A1, b1v.x, b1v.y);
            mma16(acc[1][3], A1, b1v.z, b1v.w);
        }
        __syncthreads();   // As dead; reuse as reduction scratch

        // --- k-split reduction ---
        if (ws != 0) {
            #pragma unroll
            for (int mf = 0; mf < 2; mf++)
                #pragma unroll
                for (int nf = 0; nf < 4; nf++) {
                    int grp = mf * 4 + nf;
                    *(float4*)&redbuf[(((wq * 3 + (ws - 1)) * 8 + grp) * 32 + lane) * 4]
                        = *(float4*)acc[mf][nf];
                }
        }
        __syncthreads();
        if (ws == 0) {
            #pragma unroll
            for (int s = 0; s < 3; s++)
                #pragma unroll
                for (int mf = 0; mf < 2; mf++)
                    #pragma unroll
                    for (int nf = 0; nf < 4; nf++) {
                        int grp = mf * 4 + nf;
                        float4 r = *(const float4*)&redbuf[(((wq * 3 + s) * 8 + grp) * 32 + lane) * 4];
                        acc[mf][nf][0] += r.x; acc[mf][nf][1] += r.y;
                        acc[mf][nf][2] += r.z; acc[mf][nf][3] += r.w;
                    }
            #pragma unroll
            for (int mf = 0; mf < 2; mf++)
                #pragma unroll
                for (int nf = 0; nf < 4; nf++) {
                    int row = mf * 16 + gid;
                    int col = wq * 32 + nf * 8 + tig * 2;
                    *(float2*)&gatebuf[row * 68 + col]       = make_float2(acc[mf][nf][0], acc[mf][nf][1]);
                    *(float2*)&gatebuf[(row + 8) * 68 + col] = make_float2(acc[mf][nf][2], acc[mf][nf][3]);
                }
        }
        __syncthreads();

        // --- fused LSTM epilogue (2 cells per thread) ---
        float h0, h1;
        {
            float4 gA = *(const float4*)&gatebuf[b_loc * 68 + hloc0 * 4];
            float4 gB = *(const float4*)&gatebuf[b_loc * 68 + hloc0 * 4 + 4];
            float f0 = sigf(gA.x + pA.x), i0 = sigf(gA.y + pA.y);
            float gg0 = tanhfast(gA.z + pA.z), o0 = sigf(gA.w + pA.w);
            float f1 = sigf(gB.x + pB.x), i1 = sigf(gB.y + pB.y);
            float gg1 = tanhfast(gB.z + pB.z), o1 = sigf(gB.w + pB.w);
            c0 = f0 * c0 + i0 * gg0;
            c1 = f1 * c1 + i1 * gg1;
            h0 = o0 * tanhfast(c0);
            h1 = o1 * tanhfast(c1);
            g_hFh[wb][hoff32] = packh2(h0, h1);   // fp16 h for next step
        }

        // --- arrive, then non-critical work in the barrier shadow ---
        __syncthreads();
        if (tid == 0) red_release(&g_bar[bg]);

        *(float2*)&out[(size_t)t * (BATCH * HID) + (size_t)bglob * HID + hg] = make_float2(h0, h1);
        if (t == T_STEPS - 1) {
            size_t tail = (size_t)T_STEPS * (BATCH * HID);
            *(float2*)&out[tail + (size_t)bglob * HID + hg]                         = make_float2(h0, h1);
            *(float2*)&out[tail + (size_t)(BATCH * HID) + (size_t)bglob * HID + hg] = make_float2(c0, c1);
        }

        // wait for pre[t+1] readiness (producer gemm runs concurrently)
        const int tn = (t + 1 < T_STEPS) ? t + 1 : t;
        if (tid == 0 && t + 1 < T_STEPS) {
            while (ld_acq(&g_tcnt[tn]) < 32u) { }
        }
        __syncthreads();
        {   // prefetch pre[tn]; overlaps the g_bar spin below
            const float* prp = prbase + (size_t)tn * (BATCH * GCOLS);
            pA = *(const float4*)prp;
            pB = *(const float4*)(prp + 4);
        }

        if (tid == 0) {
            const unsigned int tgt = 32u * (unsigned)(t + 1);
            while (ld_acq(&g_bar[bg]) < tgt) { }
        }
        __syncthreads();
    }
}

// ---------------- launch ----------------
extern "C" void kernel_launch(void* const* d_in, const int* in_sizes, int n_in,
                              void* d_out, int out_size) {
    const float* X  = (const float*)d_in[0];
    const float* Wf = (const float*)d_in[1];
    const float* bf = (const float*)d_in[2];
    const float* Wi = (const float*)d_in[3];
    const float* bi = (const float*)d_in[4];
    const float* Wg = (const float*)d_in[5];
    const float* bg = (const float*)d_in[6];
    const float* Wo = (const float*)d_in[7];
    const float* bo = (const float*)d_in[8];
    float* out = (float*)d_out;

    static cudaStream_t s2 = nullptr;
    static cudaEvent_t evFork = nullptr, evJoin = nullptr;
    static int once = 0;
    if (!once) {
        cudaFuncSetAttribute(lstm_persist, cudaFuncAttributeMaxDynamicSharedMemorySize, 107008);
        cudaStreamCreateWithFlags(&s2, cudaStreamNonBlocking);
        cudaEventCreateWithFlags(&evFork, cudaEventDisableTiming);
        cudaEventCreateWithFlags(&evJoin, cudaEventDisableTiming);
        once = 1;
    }

    // setup chain on the launch stream
    pack_w<<<2048, 256>>>(Wf, bf, Wi, bi, Wg, bg, Wo, bo);
    pack_x<<<65536, 256>>>(X);
    init_state<<<256, 256>>>();

    // fork: gemm_pre runs concurrently on s2, lstm_persist on the launch stream
    cudaEventRecord(evFork, 0);
    cudaStreamWaitEvent(s2, evFork, 0);
    gemm_pre<<<dim3(GCOLS / 128, 65536 / 64), 256, 0, s2>>>();
    cudaEventRecord(evJoin, s2);

    lstm_persist<<<128, 256, 107008>>>(out);

    // join: launch stream waits for gemm branch before capture ends
    cudaStreamWaitEvent(0, evJoin, 0);
}

// round 14
// speedup vs baseline: 1.1904x; 1.1904x over previous
#include <cuda_runtime.h>
#include <cuda_fp16.h>
#include <cstdint>

#define T_STEPS 512
#define BATCH   128
#define HID     512
#define GCOLS   2048   // 4*HID, interleaved: j = 4*h + gate (0=f,1=i,2=g,3=o)
#define KDIM    512

// ---------------- static device scratch ----------------
// fp16 fragment-packed layouts (m16n8k16). Chunk = 32 lanes x 4 uint32 = 512B.
__device__ __align__(256) uint32_t g_Xh[4096u * 32 * 128];     // X fp16 frags (64MB) [mgrp][ksl][lane][4]
__device__ __align__(256) uint32_t g_Wxh[128 * 32 * 128];      // Wx fp16 frags [n16][ksl][lane][4]
__device__ __align__(256) uint32_t g_Whh[128 * 32 * 128];      // Wh fp16 frags [n16][ksl][lane][4]
__device__ __align__(256) float    g_bias[GCOLS];
__device__ __align__(256) float    g_pre[(size_t)T_STEPS * BATCH * GCOLS];  // x-proj + bias (fp32)
__device__ __align__(256) uint32_t g_hFh[2][8 * 32 * 128];     // h fp16 frags [mg][ksl][lane][4], dbl-buf
__device__ unsigned int g_bar[4];                              // per-batch-group step barrier

// ---------------- helpers ----------------
__device__ __forceinline__ void cp16(void* s, const void* g) {
    uint32_t sa = (uint32_t)__cvta_generic_to_shared(s);
    asm volatile("cp.async.cg.shared.global [%0], [%1], 16;" :: "r"(sa), "l"(g));
}
__device__ __forceinline__ void cp_commit() { asm volatile("cp.async.commit_group;"); }
__device__ __forceinline__ void cp_wait0()  { asm volatile("cp.async.wait_group 0;"); }
__device__ __forceinline__ void cp_wait1()  { asm volatile("cp.async.wait_group 1;"); }

__device__ __forceinline__ void mma16(float* d, const uint32_t* a, uint32_t b0, uint32_t b1) {
    asm volatile(
        "mma.sync.aligned.m16n8k16.row.col.f32.f16.f16.f32 "
        "{%0,%1,%2,%3}, {%4,%5,%6,%7}, {%8,%9}, {%0,%1,%2,%3};"
        : "+f"(d[0]), "+f"(d[1]), "+f"(d[2]), "+f"(d[3])
        : "r"(a[0]), "r"(a[1]), "r"(a[2]), "r"(a[3]), "r"(b0), "r"(b1));
}

__device__ __forceinline__ float sigf(float x) {
    return __fdividef(1.0f, 1.0f + __expf(-x));
}
__device__ __forceinline__ float tanhfast(float x) {
    float e = __expf(2.0f * x);
    return 1.0f - __fdividef(2.0f, e + 1.0f);
}
__device__ __forceinline__ uint32_t packh2(float lo, float hi) {
    return ((uint32_t)__half_as_ushort(__float2half_rn(hi)) << 16)
         | (uint32_t)__half_as_ushort(__float2half_rn(lo));
}

__device__ __forceinline__ void red_release(unsigned int* p) {
    asm volatile("red.release.gpu.add.u32 [%0], %1;" :: "l"(p), "r"(1u) : "memory");
}
__device__ __forceinline__ unsigned int ld_acq(unsigned int* p) {
    unsigned int v;
    asm volatile("ld.acquire.gpu.u32 %0, [%1];" : "=r"(v) : "l"(p) : "memory");
    return v;
}

// ---------------- pack: Wx + Wh fp16 frags + bias ----------------
__global__ void pack_w(const float* __restrict__ Wf, const float* __restrict__ bf,
                       const float* __restrict__ Wi, const float* __restrict__ bi,
                       const float* __restrict__ Wg, const float* __restrict__ bg_,
                       const float* __restrict__ Wo, const float* __restrict__ bo) {
    unsigned idx = blockIdx.x * 256u + threadIdx.x;  // 0..524287
    int reg = idx & 3, lane = (idx >> 2) & 31, ksl = (idx >> 7) & 31, n16 = idx >> 12;
    int g = lane >> 2, t = lane & 3;
    int n = n16 * 16 + (reg >> 1) * 8 + g;         // B-frag: reg>>1 selects n8 half
    int kb = ksl * 16 + (reg & 1) * 8 + 2 * t;     // reg&1 selects k half (b0/b1)
    int h = n >> 2, gate = n & 3;
    const float* W = (gate == 0) ? Wf : (gate == 1) ? Wi : (gate == 2) ? Wg : Wo;
    g_Wxh[idx] = packh2(W[h * 1024 + kb],       W[h * 1024 + kb + 1]);
    g_Whh[idx] = packh2(W[h * 1024 + 512 + kb], W[h * 1024 + 512 + kb + 1]);
    if (idx < GCOLS) {
        int j = idx, h2 = j >> 2, g2 = j & 3;
        const float* bb = (g2 == 0) ? bf : (g2 == 1) ? bi : (g2 == 2) ? bg_ : bo;
        g_bias[j] = bb[h2];
    }
}

// ---------------- pack: X fp16 frags ----------------
__global__ void pack_x(const float* __restrict__ X) {
    unsigned idx = blockIdx.x * 256u + threadIdx.x;  // 0..16777215
    int reg = idx & 3, lane = (idx >> 2) & 31, ksl = (idx >> 7) & 31;
    unsigned mgrp = idx >> 12;
    int g = lane >> 2, t = lane & 3;
    unsigned m = mgrp * 16 + (reg & 1) * 8 + g;    // A-frag: reg&1 selects row half
    int kb = ksl * 16 + (reg >> 1) * 8 + 2 * t;    // reg>>1 selects k half
    const float* p = X + (size_t)m * 512 + kb;
    g_Xh[idx] = packh2(p[0], p[1]);
}

__global__ void init_state() {
    unsigned i = blockIdx.x * 256u + threadIdx.x;
    if (i < 4) g_bar[i] = 0;
    if (i < 2u * 8 * 32 * 128) ((uint32_t*)g_hFh)[i] = 0u;
}

// ---------------- precompute GEMM: pre = X @ WxT + bias (R5-exact) ----------------
// BM=64 BN=128 BK=32, 256 threads, warps 2(M) x 4(N), warp tile 32x32. n-fastest grid.
__global__ __launch_bounds__(256) void gemm_pre() {
    __shared__ __align__(128) uint32_t Asm[2][8 * 128];    // 4 mgrp x 2 ksl chunks
    __shared__ __align__(128) uint32_t Bsm[2][16 * 128];   // 8 n16  x 2 ksl chunks
    const int tid = threadIdx.x;
    const int n16_0 = blockIdx.x * 8;        // n0 = blockIdx.x*128
    const int mgrp0 = blockIdx.y * 4;        // m0 = blockIdx.y*64
    const int n0 = n16_0 * 16, m0 = mgrp0 * 16;
    const int warp = tid >> 5, lane = tid & 31;
    const int wm = warp >> 2, wn = warp & 3;
    const int gid = lane >> 2, tig = lane & 3;

    float acc[2][4][4];
    #pragma unroll
    for (int i0 = 0; i0 < 2; i0++)
        #pragma unroll
        for (int i1 = 0; i1 < 4; i1++)
            #pragma unroll
            for (int i2 = 0; i2 < 4; i2++) acc[i0][i1][i2] = 0.0f;

    auto load_tiles = [&](int buf, int kt) {
        {   // A: 8 chunks, 1 slot per thread
            int chunk = tid >> 5, ln = tid & 31;
            unsigned gc = (mgrp0 + (chunk >> 1)) * 32u + 2 * kt + (chunk & 1);
            cp16(&Asm[buf][chunk * 128 + ln * 4], g_Xh + (size_t)gc * 128 + ln * 4);
        }
        #pragma unroll
        for (int i = 0; i < 2; i++) {   // B: 16 chunks, 2 slots per thread
            int slot = tid * 2 + i;
            int chunk = slot >> 5, ln = slot & 31;
            unsigned gc = (n16_0 + (chunk >> 1)) * 32u + 2 * kt + (chunk & 1);
            cp16(&Bsm[buf][chunk * 128 + ln * 4], g_Wxh + (size_t)gc * 128 + ln * 4);
        }
        cp_commit();
    };

    load_tiles(0, 0);
    for (int kt = 0; kt < 16; kt++) {
        if (kt < 15) { load_tiles((kt + 1) & 1, kt + 1); cp_wait1(); }
        else cp_wait0();
        __syncthreads();
        const uint32_t* A_ = Asm[kt & 1];
        const uint32_t* B_ = Bsm[kt & 1];
        #pragma unroll
        for (int ksll = 0; ksll < 2; ksll++) {
            uint4 av0 = *(const uint4*)&A_[((wm * 2 + 0) * 2 + ksll) * 128 + lane * 4];
            uint4 av1 = *(const uint4*)&A_[((wm * 2 + 1) * 2 + ksll) * 128 + lane * 4];
            uint32_t A0[4] = {av0.x, av0.y, av0.z, av0.w};
            uint32_t A1[4] = {av1.x, av1.y, av1.z, av1.w};
            #pragma unroll
            for (int cl = 0; cl < 2; cl++) {
                uint4 bv = *(const uint4*)&B_[((wn * 2 + cl) * 2 + ksll) * 128 + lane * 4];
                mma16(acc[0][cl * 2 + 0], A0, bv.x, bv.y);
                mma16(acc[0][cl * 2 + 1], A0, bv.z, bv.w);
                mma16(acc[1][cl * 2 + 0], A1, bv.x, bv.y);
                mma16(acc[1][cl * 2 + 1], A1, bv.z, bv.w);
            }
        }
        __syncthreads();
    }

    #pragma unroll
    for (int mf = 0; mf < 2; mf++)
        #pragma unroll
        for (int nf = 0; nf < 4; nf++) {
            int row0 = m0 + wm * 32 + mf * 16 + gid;
            int col  = n0 + wn * 32 + nf * 8 + tig * 2;
            float bb0 = g_bias[col], bb1 = g_bias[col + 1];
            float2 s0 = make_float2(acc[mf][nf][0] + bb0, acc[mf][nf][1] + bb1);
            float2 s1 = make_float2(acc[mf][nf][2] + bb0, acc[mf][nf][3] + bb1);
            *(float2*)&g_pre[(size_t)row0 * GCOLS + col]       = s0;
            *(float2*)&g_pre[(size_t)(row0 + 8) * GCOLS + col] = s1;
        }
}

// ---------------- persistent recurrent kernel (R5 datapath + lean tail) ----------------
// Grid: 128 blocks = 4 batch-groups x 32 n-slices. 256 threads (8 warps = S4 x Q2).
__global__ __launch_bounds__(256) void lstm_persist(float* __restrict__ out) {
    extern __shared__ uint32_t sm32[];
    uint32_t* WhS = sm32;                    // 16384 u32 (64KB): [n16l(4)][ksl(32)][lane][4]
    uint32_t* As  = sm32 + 16384;            // 8192 u32 (32KB): [mgl(2)][ksl(32)][lane][4]
    float* redbuf  = (float*)As;             // reuse (6144 floats <= 8192 u32)
    float* gatebuf = (float*)(sm32 + 16384 + 8192);   // 2176 floats

    const int tid  = threadIdx.x;
    const int lane = tid & 31;
    const int w    = tid >> 5;
    const int ws   = w >> 1;         // k-slice 0..3 (k range 128)
    const int wq   = w & 1;          // n-half 0..1
    const int gid  = lane >> 2, tig = lane & 3;

    const int bg  = blockIdx.x >> 5;       // batch group 0..3
    const int nb  = blockIdx.x & 31;       // n-slice 0..31
    const int b0_ = bg * 32;
    const int n0  = nb * 64;

    // --- load Wh slice (64KB = 4096 cp16 / 256 thr = 16 each) ---
    {
        const uint32_t* src = g_Whh + (size_t)nb * 16384;
        #pragma unroll
        for (int i = 0; i < 16; i++) {
            int c = tid + i * 256;
            cp16(&WhS[c * 4], src + (size_t)c * 4);
        }
        cp_commit(); cp_wait0();
        __syncthreads();
    }

    // epilogue cell mapping (fixed): 2 cells (bglob, hg), (bglob, hg+1)
    const int b_loc = tid >> 3;            // 0..31
    const int hloc0 = (tid & 7) * 2;       // 0..14 even
    const int bglob = b0_ + b_loc;
    const int hg    = nb * 16 + hloc0;
    // h frag-layout offset: both cells share one uint32 (k pair)
    const int mg_h = bglob >> 4;
    const int rr   = bglob & 15;
    const int g_m  = rr & 7, hi_m = rr >> 3;
    const int ksl_h = hg >> 4;
    const int kk   = hg & 15;
    const int hi_k = kk >> 3, tig_k = (kk >> 1) & 3;
    const int hoff32 = ((mg_h * 32 + ksl_h) * 32 + (g_m * 4 + tig_k)) * 4 + (hi_m + 2 * hi_k);

    float c0 = 0.0f, c1 = 0.0f;

    // prefetch pre[0]
    const float* prbase = g_pre + (size_t)bglob * GCOLS + n0 + hloc0 * 4;
    float4 pA = *(const float4*)prbase;
    float4 pB = *(const float4*)(prbase + 4);

    for (int t = 0; t < T_STEPS; t++) {
        const int rb = t & 1, wb = rb ^ 1;

        // --- stage h[rb]: 32KB = 2048 cp16 / 256 thr = 8 each ---
        const uint32_t* src = g_hFh[rb] + bg * 8192;
        #pragma unroll
        for (int i = 0; i < 8; i++) {
            int c = tid + i * 256;
            cp16(&As[c * 4], src + c * 4);
        }
        cp_commit();
        cp_wait0();
        __syncthreads();

        // --- mainloop: warp (ws,wq): 32m x 32n, k in [ws*128, +128) ---
        float acc[2][4][4];
        #pragma unroll
        for (int i0 = 0; i0 < 2; i0++)
            #pragma unroll
            for (int i1 = 0; i1 < 4; i1++)
                #pragma unroll
                for (int i2 = 0; i2 < 4; i2++) acc[i0][i1][i2] = 0.0f;

        #pragma unroll
        for (int ksl = 0; ksl < 8; ksl++) {
            const int kg = ws * 8 + ksl;
            uint4 a0v = *(const uint4*)&As[(0 * 32 + kg) * 128 + lane * 4];
            uint4 a1v = *(const uint4*)&As[(1 * 32 + kg) * 128 + lane * 4];
            uint4 b0v = *(const uint4*)&WhS[((wq * 2 + 0) * 32 + kg) * 128 + lane * 4];
            uint4 b1v = *(const uint4*)&WhS[((wq * 2 + 1) * 32 + kg) * 128 + lane * 4];
            uint32_t A0[4] = {a0v.x, a0v.y, a0v.z, a0v.w};
            uint32_t A1[4] = {a1v.x, a1v.y, a1v.z, a1v.w};
            mma16(acc[0][0], A0, b0v.x, b0v.y);
            mma16(acc[0][1], A0, b0v.z, b0v.w);
            mma16(acc[0][2], A0, b1v.x, b1v.y);
            mma16(acc[0][3], A0, b1v.z, b1v.w);
            mma16(acc[1][0], A1, b0v.x, b0v.y);
            mma16(acc[1][1], A1, b0v.z, b0v.w);
            mma16(acc[1][2], A1, b1v.x, b1v.y);
            mma16(acc[1][3], A1, b1v.z, b1v.w);
        }
        __syncthreads();   // As dead; reuse as reduction scratch

        // --- k-split reduction ---
        if (ws != 0) {
            #pragma unroll
            for (int mf = 0; mf < 2; mf++)
                #pragma unroll
                for (int nf = 0; nf < 4; nf++) {
                    int grp = mf * 4 + nf;
                    *(float4*)&redbuf[(((wq * 3 + (ws - 1)) * 8 + grp) * 32 + lane) * 4]
                        = *(float4*)acc[mf][nf];
                }
        }
        __syncthreads();
        if (ws == 0) {
            #pragma unroll
            for (int s = 0; s < 3; s++)
                #pragma unroll
                for (int mf = 0; mf < 2; mf++)
                    #pragma unroll
                    for (int nf = 0; nf < 4; nf++) {
                        int grp = mf * 4 + nf;
                        float4 r = *(const float4*)&redbuf[(((wq * 3 + s) * 8 + grp) * 32 + lane) * 4];
                        acc[mf][nf][0] += r.x; acc[mf][nf][1] += r.y;
                        acc[mf][nf][2] += r.z; acc[mf][nf][3] += r.w;
                    }
            #pragma unroll
            for (int mf = 0; mf < 2; mf++)
                #pragma unroll
                for (int nf = 0; nf < 4; nf++) {
                    int row = mf * 16 + gid;
                    int col = wq * 32 + nf * 8 + tig * 2;
                    *(float2*)&gatebuf[row * 68 + col]       = make_float2(acc[mf][nf][0], acc[mf][nf][1]);
                    *(float2*)&gatebuf[(row + 8) * 68 + col] = make_float2(acc[mf][nf][2], acc[mf][nf][3]);
                }
        }
        __syncthreads();

        // --- fused LSTM epilogue (2 cells per thread) ---
        float h0, h1;
        {
            float4 gA = *(const float4*)&gatebuf[b_loc * 68 + hloc0 * 4];
            float4 gB = *(const float4*)&gatebuf[b_loc * 68 + hloc0 * 4 + 4];
            float f0 = sigf(gA.x + pA.x), i0 = sigf(gA.y + pA.y);
            float gg0 = tanhfast(gA.z + pA.z), o0 = sigf(gA.w + pA.w);
            float f1 = sigf(gB.x + pB.x), i1 = sigf(gB.y + pB.y);
            float gg1 = tanhfast(gB.z + pB.z), o1 = sigf(gB.w + pB.w);
            c0 = f0 * c0 + i0 * gg0;
            c1 = f1 * c1 + i1 * gg1;
            h0 = o0 * tanhfast(c0);
            h1 = o1 * tanhfast(c1);
            g_hFh[wb][hoff32] = packh2(h0, h1);   // fp16 h for next step
        }

        // --- arrive, then non-critical work in the barrier shadow ---
        __syncthreads();
        if (tid == 0) red_release(&g_bar[bg]);

        *(float2*)&out[(size_t)t * (BATCH * HID) + (size_t)bglob * HID + hg] = make_float2(h0, h1);
        if (t == T_STEPS - 1) {
            size_t tail = (size_t)T_STEPS * (BATCH * HID);
            *(float2*)&out[tail + (size_t)bglob * HID + hg]                         = make_float2(h0, h1);
            *(float2*)&out[tail + (size_t)(BATCH * HID) + (size_t)bglob * HID + hg] = make_float2(c0, c1);
        }

        // single tid0 spin + ONE sync (lean tail)
        if (tid == 0) {
            const unsigned int tgt = 32u * (unsigned)(t + 1);
            while (ld_acq(&g_bar[bg]) < tgt) { }
        }
        __syncthreads();

        // prefetch pre[t+1]; consumed only at the NEXT epilogue, so its DRAM
        // latency hides under the entire next stage + mainloop + reduction
        {
            const int tn = (t + 1 < T_STEPS) ? t + 1 : t;
            const float* prp = prbase + (size_t)tn * (BATCH * GCOLS);
            pA = *(const float4*)prp;
            pB = *(const float4*)(prp + 4);
        }
    }
}

// ---------------- launch ----------------
extern "C" void kernel_launch(void* const* d_in, const int* in_sizes, int n_in,
                              void* d_out, int out_size) {
    const float* X  = (const float*)d_in[0];
    const float* Wf = (const float*)d_in[1];
    const float* bf = (const float*)d_in[2];
    const float* Wi = (const float*)d_in[3];
    const float* bi = (const float*)d_in[4];
    const float* Wg = (const float*)d_in[5];
    const float* bg = (const float*)d_in[6];
    const float* Wo = (const float*)d_in[7];
    const float* bo = (const float*)d_in[8];
    float* out = (float*)d_out;

    static int once = 0;
    if (!once) {
        cudaFuncSetAttribute(lstm_persist, cudaFuncAttributeMaxDynamicSharedMemorySize, 107008);
        once = 1;
    }

    pack_w<<<2048, 256>>>(Wf, bf, Wi, bi, Wg, bg, Wo, bo);
    pack_x<<<65536, 256>>>(X);
    init_state<<<256, 256>>>();
    gemm_pre<<<dim3(GCOLS / 128, 65536 / 64), 256>>>();
    lstm_persist<<<128, 256, 107008>>>(out);
}

// round 16
// speedup vs baseline: 1.2639x; 1.0618x over previous
#include <cuda_runtime.h>
#include <cuda_fp16.h>
#include <cstdint>

#define T_STEPS 512
#define BATCH   128
#define HID     512
#define GCOLS   2048   // 4*HID, interleaved: j = 4*h + gate (0=f,1=i,2=g,3=o)
#define KDIM    512

// ---------------- static device scratch ----------------
// fp16 fragment-packed layouts (m16n8k16). Chunk = 32 lanes x 4 uint32 = 512B.
__device__ __align__(256) uint32_t g_Xh[4096u * 32 * 128];     // X fp16 frags (64MB) [mgrp][ksl][lane][4]
__device__ __align__(256) uint32_t g_Wxh[128 * 32 * 128];      // Wx fp16 frags [n16][ksl][lane][4]
__device__ __align__(256) uint32_t g_Whh[128 * 32 * 128];      // Wh fp16 frags [n16][ksl][lane][4]
__device__ __align__(256) float    g_bias[GCOLS];
__device__ __align__(256) uint32_t g_preh[(size_t)T_STEPS * BATCH * GCOLS / 2]; // x-proj + bias (fp16x2, 256MB)
__device__ __align__(256) uint32_t g_hFh[2][8 * 32 * 128];     // h fp16 frags [mg][ksl][lane][4], dbl-buf
__device__ unsigned int g_bar[4];                              // per-batch-group step barrier

// ---------------- helpers ----------------
__device__ __forceinline__ void cp16(void* s, const void* g) {
    uint32_t sa = (uint32_t)__cvta_generic_to_shared(s);
    asm volatile("cp.async.cg.shared.global [%0], [%1], 16;" :: "r"(sa), "l"(g));
}
__device__ __forceinline__ void cp_commit() { asm volatile("cp.async.commit_group;"); }
__device__ __forceinline__ void cp_wait0()  { asm volatile("cp.async.wait_group 0;"); }
__device__ __forceinline__ void cp_wait1()  { asm volatile("cp.async.wait_group 1;"); }

__device__ __forceinline__ void mma16(float* d, const uint32_t* a, uint32_t b0, uint32_t b1) {
    asm volatile(
        "mma.sync.aligned.m16n8k16.row.col.f32.f16.f16.f32 "
        "{%0,%1,%2,%3}, {%4,%5,%6,%7}, {%8,%9}, {%0,%1,%2,%3};"
        : "+f"(d[0]), "+f"(d[1]), "+f"(d[2]), "+f"(d[3])
        : "r"(a[0]), "r"(a[1]), "r"(a[2]), "r"(a[3]), "r"(b0), "r"(b1));
}

__device__ __forceinline__ float sigf(float x) {
    return __fdividef(1.0f, 1.0f + __expf(-x));
}
__device__ __forceinline__ float tanhfast(float x) {
    float e = __expf(2.0f * x);
    return 1.0f - __fdividef(2.0f, e + 1.0f);
}
__device__ __forceinline__ uint32_t packh2(float lo, float hi) {
    return ((uint32_t)__half_as_ushort(__float2half_rn(hi)) << 16)
         | (uint32_t)__half_as_ushort(__float2half_rn(lo));
}
__device__ __forceinline__ float2 unpackh2(uint32_t v) {
    return __half22float2(*(const __half2*)&v);
}

__device__ __forceinline__ void red_release(unsigned int* p) {
    asm volatile("red.release.gpu.add.u32 [%0], %1;" :: "l"(p), "r"(1u) : "memory");
}
__device__ __forceinline__ unsigned int ld_acq(unsigned int* p) {
    unsigned int v;
    asm volatile("ld.acquire.gpu.u32 %0, [%1];" : "=r"(v) : "l"(p) : "memory");
    return v;
}

// ---------------- pack: Wx + Wh fp16 frags + bias ----------------
__global__ void pack_w(const float* __restrict__ Wf, const float* __restrict__ bf,
                       const float* __restrict__ Wi, const float* __restrict__ bi,
                       const float* __restrict__ Wg, const float* __restrict__ bg_,
                       const float* __restrict__ Wo, const float* __restrict__ bo) {
    unsigned idx = blockIdx.x * 256u + threadIdx.x;  // 0..524287
    int reg = idx & 3, lane = (idx >> 2) & 31, ksl = (idx >> 7) & 31, n16 = idx >> 12;
    int g = lane >> 2, t = lane & 3;
    int n = n16 * 16 + (reg >> 1) * 8 + g;         // B-frag: reg>>1 selects n8 half
    int kb = ksl * 16 + (reg & 1) * 8 + 2 * t;     // reg&1 selects k half (b0/b1)
    int h = n >> 2, gate = n & 3;
    const float* W = (gate == 0) ? Wf : (gate == 1) ? Wi : (gate == 2) ? Wg : Wo;
    g_Wxh[idx] = packh2(W[h * 1024 + kb],       W[h * 1024 + kb + 1]);
    g_Whh[idx] = packh2(W[h * 1024 + 512 + kb], W[h * 1024 + 512 + kb + 1]);
    if (idx < GCOLS) {
        int j = idx, h2 = j >> 2, g2 = j & 3;
        const float* bb = (g2 == 0) ? bf : (g2 == 1) ? bi : (g2 == 2) ? bg_ : bo;
        g_bias[j] = bb[h2];
    }
}

// ---------------- pack: X fp16 frags (smem-staged, coalesced both sides) ----------------
__global__ __launch_bounds__(256) void pack_x(const float* __restrict__ X) {
    __shared__ float xs[16 * 512];                 // 32KB: one 16-row m-group
    const int mgrp = blockIdx.x;                   // 0..4095
    const int tid = threadIdx.x;
    // coalesced load: 8192 floats = 2048 float4
    const float4* src = (const float4*)(X + (size_t)mgrp * 16 * 512);
    float4* dst = (float4*)xs;
    #pragma unroll
    for (int i = 0; i < 8; i++) dst[tid + i * 256] = src[tid + i * 256];
    __syncthreads();
    // coalesced store: 4096 uint32 frags for this m-group
    uint32_t* outp = g_Xh + (size_t)mgrp * 4096;
    #pragma unroll
    for (int i = 0; i < 16; i++) {
        unsigned o = i * 256 + tid;                // local frag index 0..4095
        int reg = o & 3, lane = (o >> 2) & 31, ksl = (o >> 7) & 31;
        int g = lane >> 2, t = lane & 3;
        int m = (reg & 1) * 8 + g;                 // local row 0..15
        int kb = ksl * 16 + (reg >> 1) * 8 + 2 * t;
        outp[o] = packh2(xs[m * 512 + kb], xs[m * 512 + kb + 1]);
    }
}

__global__ void init_state() {
    unsigned i = blockIdx.x * 256u + threadIdx.x;
    if (i < 4) g_bar[i] = 0;
    if (i < 2u * 8 * 32 * 128) ((uint32_t*)g_hFh)[i] = 0u;
}

// ---------------- precompute GEMM: pre = X @ WxT + bias (fp16 frags, fp32 accum, fp16 out) ----------------
// BM=64 BN=128 BK=32, 256 threads, warps 2(M) x 4(N), warp tile 32x32. n-fastest grid.
// launch_bounds minBlocks=4 forces regs<=64 -> 4 blocks/SM (was 3 at 80 regs).
__global__ __launch_bounds__(256, 4) void gemm_pre() {
    __shared__ __align__(128) uint32_t Asm[2][8 * 128];    // 4 mgrp x 2 ksl chunks
    __shared__ __align__(128) uint32_t Bsm[2][16 * 128];   // 8 n16  x 2 ksl chunks
    const int tid = threadIdx.x;
    const int n16_0 = blockIdx.x * 8;        // n0 = blockIdx.x*128
    const int mgrp0 = blockIdx.y * 4;        // m0 = blockIdx.y*64
    const int n0 = n16_0 * 16, m0 = mgrp0 * 16;
    const int warp = tid >> 5, lane = tid & 31;
    const int wm = warp >> 2, wn = warp & 3;
    const int gid = lane >> 2, tig = lane & 3;

    float acc[2][4][4];
    #pragma unroll
    for (int i0 = 0; i0 < 2; i0++)
        #pragma unroll
        for (int i1 = 0; i1 < 4; i1++)
            #pragma unroll
            for (int i2 = 0; i2 < 4; i2++) acc[i0][i1][i2] = 0.0f;

    auto load_tiles = [&](int buf, int kt) {
        {   // A: 8 chunks, 1 slot per thread
            int chunk = tid >> 5, ln = tid & 31;
            unsigned gc = (mgrp0 + (chunk >> 1)) * 32u + 2 * kt + (chunk & 1);
            cp16(&Asm[buf][chunk * 128 + ln * 4], g_Xh + (size_t)gc * 128 + ln * 4);
        }
        #pragma unroll
        for (int i = 0; i < 2; i++) {   // B: 16 chunks, 2 slots per thread
            int slot = tid * 2 + i;
            int chunk = slot >> 5, ln = slot & 31;
            unsigned gc = (n16_0 + (chunk >> 1)) * 32u + 2 * kt + (chunk & 1);
            cp16(&Bsm[buf][chunk * 128 + ln * 4], g_Wxh + (size_t)gc * 128 + ln * 4);
        }
        cp_commit();
    };

    load_tiles(0, 0);
    for (int kt = 0; kt < 16; kt++) {
        if (kt < 15) { load_tiles((kt + 1) & 1, kt + 1); cp_wait1(); }
        else cp_wait0();
        __syncthreads();
        const uint32_t* A_ = Asm[kt & 1];
        const uint32_t* B_ = Bsm[kt & 1];
        #pragma unroll
        for (int ksll = 0; ksll < 2; ksll++) {
            uint4 av0 = *(const uint4*)&A_[((wm * 2 + 0) * 2 + ksll) * 128 + lane * 4];
            uint4 av1 = *(const uint4*)&A_[((wm * 2 + 1) * 2 + ksll) * 128 + lane * 4];
            uint32_t A0[4] = {av0.x, av0.y, av0.z, av0.w};
            uint32_t A1[4] = {av1.x, av1.y, av1.z, av1.w};
            #pragma unroll
            for (int cl = 0; cl < 2; cl++) {
                uint4 bv = *(const uint4*)&B_[((wn * 2 + cl) * 2 + ksll) * 128 + lane * 4];
                mma16(acc[0][cl * 2 + 0], A0, bv.x, bv.y);
                mma16(acc[0][cl * 2 + 1], A0, bv.z, bv.w);
                mma16(acc[1][cl * 2 + 0], A1, bv.x, bv.y);
                mma16(acc[1][cl * 2 + 1], A1, bv.z, bv.w);
            }
        }
        __syncthreads();
    }

    #pragma unroll
    for (int mf = 0; mf < 2; mf++)
        #pragma unroll
        for (int nf = 0; nf < 4; nf++) {
            int row0 = m0 + wm * 32 + mf * 16 + gid;
            int col  = n0 + wn * 32 + nf * 8 + tig * 2;
            float bb0 = g_bias[col], bb1 = g_bias[col + 1];
            g_preh[((size_t)row0 * GCOLS + col) >> 1]
                = packh2(acc[mf][nf][0] + bb0, acc[mf][nf][1] + bb1);
            g_preh[((size_t)(row0 + 8) * GCOLS + col) >> 1]
                = packh2(acc[mf][nf][2] + bb0, acc[mf][nf][3] + bb1);
        }
}

// ---------------- persistent recurrent kernel (R5-exact; pre prefetch now fp16x8) ----------------
// Grid: 128 blocks = 4 batch-groups x 32 n-slices. 256 threads (8 warps = S4 x Q2).
__global__ __launch_bounds__(256) void lstm_persist(float* __restrict__ out) {
    extern __shared__ uint32_t sm32[];
    uint32_t* WhS = sm32;                    // 16384 u32 (64KB): [n16l(4)][ksl(32)][lane][4]
    uint32_t* As  = sm32 + 16384;            // 8192 u32 (32KB): [mgl(2)][ksl(32)][lane][4]
    float* redbuf  = (float*)As;             // reuse (6144 floats <= 8192 u32)
    float* gatebuf = (float*)(sm32 + 16384 + 8192);   // 2176 floats

    const int tid  = threadIdx.x;
    const int lane = tid & 31;
    const int w    = tid >> 5;
    const int ws   = w >> 1;         // k-slice 0..3 (k range 128)
    const int wq   = w & 1;          // n-half 0..1
    const int gid  = lane >> 2, tig = lane & 3;

    const int bg  = blockIdx.x >> 5;       // batch group 0..3
    const int nb  = blockIdx.x & 31;       // n-slice 0..31
    const int b0_ = bg * 32;
    const int n0  = nb * 64;

    // --- load Wh slice (64KB = 4096 cp16 / 256 thr = 16 each) ---
    {
        const uint32_t* src = g_Whh + (size_t)nb * 16384;
        #pragma unroll
        for (int i = 0; i < 16; i++) {
            int c = tid + i * 256;
            cp16(&WhS[c * 4], src + (size_t)c * 4);
        }
        cp_commit(); cp_wait0();
        __syncthreads();
    }

    // epilogue cell mapping (fixed): 2 cells (bglob, hg), (bglob, hg+1)
    const int b_loc = tid >> 3;            // 0..31
    const int hloc0 = (tid & 7) * 2;       // 0..14 even
    const int bglob = b0_ + b_loc;
    const int hg    = nb * 16 + hloc0;
    // h frag-layout offset: both cells share one uint32 (k pair)
    const int mg_h = bglob >> 4;
    const int rr   = bglob & 15;
    const int g_m  = rr & 7, hi_m = rr >> 3;
    const int ksl_h = hg >> 4;
    const int kk   = hg & 15;
    const int hi_k = kk >> 3, tig_k = (kk >> 1) & 3;
    const int hoff32 = ((mg_h * 32 + ksl_h) * 32 + (g_m * 4 + tig_k)) * 4 + (hi_m + 2 * hi_k);

    float c0 = 0.0f, c1 = 0.0f;

    // prefetch pre[0] (fp16 x 8 = one uint4)
    const size_t preoff = (size_t)bglob * (GCOLS / 2) + nb * 32 + hloc0 * 2;
    uint4 pv = *(const uint4*)(g_preh + preoff);

    for (int t = 0; t < T_STEPS; t++) {
        const int rb = t & 1, wb = rb ^ 1;

        // --- stage h[rb]: 32KB = 2048 cp16 / 256 thr = 8 each ---
        const uint32_t* src = g_hFh[rb] + bg * 8192;
        #pragma unroll
        for (int i = 0; i < 8; i++) {
            int c = tid + i * 256;
            cp16(&As[c * 4], src + c * 4);
        }
        cp_commit();
        cp_wait0();
        __syncthreads();

        // --- mainloop: warp (ws,wq): 32m x 32n, k in [ws*128, +128) ---
        float acc[2][4][4];
        #pragma unroll
        for (int i0 = 0; i0 < 2; i0++)
            #pragma unroll
            for (int i1 = 0; i1 < 4; i1++)
                #pragma unroll
                for (int i2 = 0; i2 < 4; i2++) acc[i0][i1][i2] = 0.0f;

        #pragma unroll
        for (int ksl = 0; ksl < 8; ksl++) {
            const int kg = ws * 8 + ksl;
            uint4 a0v = *(const uint4*)&As[(0 * 32 + kg) * 128 + lane * 4];
            uint4 a1v = *(const uint4*)&As[(1 * 32 + kg) * 128 + lane * 4];
            uint4 b0v = *(const uint4*)&WhS[((wq * 2 + 0) * 32 + kg) * 128 + lane * 4];
            uint4 b1v = *(const uint4*)&WhS[((wq * 2 + 1) * 32 + kg) * 128 + lane * 4];
            uint32_t A0[4] = {a0v.x, a0v.y, a0v.z, a0v.w};
            uint32_t A1[4] = {a1v.x, a1v.y, a1v.z, a1v.w};
            mma16(acc[0][0], A0, b0v.x, b0v.y);
            mma16(acc[0][1], A0, b0v.z, b0v.w);
            mma16(acc[0][2], A0, b1v.x, b1v.y);
            mma16(acc[0][3], A0, b1v.z, b1v.w);
            mma16(acc[1][0], A1, b0v.x, b0v.y);
            mma16(acc[1][1], A1, b0v.z, b0v.w);
            mma16(acc[1][2], A1, b1v.x, b1v.y);
            mma16(acc[1][3], A1, b1v.z, b1v.w);
        }
        __syncthreads();   // As dead; reuse as reduction scratch

        // --- k-split reduction ---
        if (ws != 0) {
            #pragma unroll
            for (int mf = 0; mf < 2; mf++)
                #pragma unroll
                for (int nf = 0; nf < 4; nf++) {
                    int grp = mf * 4 + nf;
                    *(float4*)&redbuf[(((wq * 3 + (ws - 1)) * 8 + grp) * 32 + lane) * 4]
                        = *(float4*)acc[mf][nf];
                }
        }
        __syncthreads();
        if (ws == 0) {
            #pragma unroll
            for (int s = 0; s < 3; s++)
                #pragma unroll
                for (int mf = 0; mf < 2; mf++)
                    #pragma unroll
                    for (int nf = 0; nf < 4; nf++) {
                        int grp = mf * 4 + nf;
                        float4 r = *(const float4*)&redbuf[(((wq * 3 + s) * 8 + grp) * 32 + lane) * 4];
                        acc[mf][nf][0] += r.x; acc[mf][nf][1] += r.y;
                        acc[mf][nf][2] += r.z; acc[mf][nf][3] += r.w;
                    }
            #pragma unroll
            for (int mf = 0; mf < 2; mf++)
                #pragma unroll
                for (int nf = 0; nf < 4; nf++) {
                    int row = mf * 16 + gid;
                    int col = wq * 32 + nf * 8 + tig * 2;
                    *(float2*)&gatebuf[row * 68 + col]       = make_float2(acc[mf][nf][0], acc[mf][nf][1]);
                    *(float2*)&gatebuf[(row + 8) * 68 + col] = make_float2(acc[mf][nf][2], acc[mf][nf][3]);
                }
        }
        __syncthreads();

        // --- fused LSTM epilogue (2 cells per thread) ---
        float h0, h1;
        {
            float4 gA = *(const float4*)&gatebuf[b_loc * 68 + hloc0 * 4];
            float4 gB = *(const float4*)&gatebuf[b_loc * 68 + hloc0 * 4 + 4];
            float2 q0 = unpackh2(pv.x), q1 = unpackh2(pv.y);
            float2 q2 = unpackh2(pv.z), q3 = unpackh2(pv.w);
            float f0 = sigf(gA.x + q0.x), i0 = sigf(gA.y + q0.y);
            float gg0 = tanhfast(gA.z + q1.x), o0 = sigf(gA.w + q1.y);
            float f1 = sigf(gB.x + q2.x), i1 = sigf(gB.y + q2.y);
            float gg1 = tanhfast(gB.z + q3.x), o1 = sigf(gB.w + q3.y);
            c0 = f0 * c0 + i0 * gg0;
            c1 = f1 * c1 + i1 * gg1;
            h0 = o0 * tanhfast(c0);
            h1 = o1 * tanhfast(c1);
            g_hFh[wb][hoff32] = packh2(h0, h1);   // fp16 h for next step
        }

        // --- arrive, then non-critical work in the barrier shadow (R5 order) ---
        __syncthreads();
        if (tid == 0) red_release(&g_bar[bg]);

        *(float2*)&out[(size_t)t * (BATCH * HID) + (size_t)bglob * HID + hg] = make_float2(h0, h1);
        if (t == T_STEPS - 1) {
            size_t tail = (size_t)T_STEPS * (BATCH * HID);
            *(float2*)&out[tail + (size_t)bglob * HID + hg]                         = make_float2(h0, h1);
            *(float2*)&out[tail + (size_t)(BATCH * HID) + (size_t)bglob * HID + hg] = make_float2(c0, c1);
        }
        {   // prefetch pre[t+1] while waiting (R5 shadow position)
            int tn = (t + 1 < T_STEPS) ? t + 1 : t;
            pv = *(const uint4*)(g_preh + preoff + (size_t)tn * (BATCH * GCOLS / 2));
        }

        if (tid == 0) {
            const unsigned int tgt = 32u * (unsigned)(t + 1);
            while (ld_acq(&g_bar[bg]) < tgt) { }
        }
        __syncthreads();
    }
}

// ---------------- launch ----------------
extern "C" void kernel_launch(void* const* d_in, const int* in_sizes, int n_in,
                              void* d_out, int out_size) {
    const float* X  = (const float*)d_in[0];
    const float* Wf = (const float*)d_in[1];
    const float* bf = (const float*)d_in[2];
    const float* Wi = (const float*)d_in[3];
    const float* bi = (const float*)d_in[4];
    const float* Wg = (const float*)d_in[5];
    const float* bg = (const float*)d_in[6];
    const float* Wo = (const float*)d_in[7];
    const float* bo = (const float*)d_in[8];
    float* out = (float*)d_out;

    static int once = 0;
    if (!once) {
        cudaFuncSetAttribute(lstm_persist, cudaFuncAttributeMaxDynamicSharedMemorySize, 107008);
        once = 1;
    }

    pack_w<<<2048, 256>>>(Wf, bf, Wi, bi, Wg, bg, Wo, bo);
    pack_x<<<4096, 256>>>(X);
    init_state<<<256, 256>>>();
    gemm_pre<<<dim3(GCOLS / 128, 65536 / 64), 256>>>();
    lstm_persist<<<128, 256, 107008>>>(out);
}